// round 10
// baseline (speedup 1.0000x reference)
#include <cuda_runtime.h>
#include <cuda_fp16.h>
#include <cstdint>
#include <math.h>

// Problem constants
#define BB 2
#define LL 4096
#define HH 2048
#define LK 128
#define KDIM HH          // GEMM K = H = 2048
#define NHALF HH         // GLU half width = 2048

typedef unsigned long long u64b;

// Scratch (static __device__ arrays: allocation-free per harness rules)
__device__ __half g_buf[(size_t)BB * LL * HH];   // gelu(conv) output fp16, [M=B*L, K=H]
__device__ __half w_h[(size_t)2 * HH * HH];      // W fp16, [4096, 2048]

__device__ __forceinline__ void cp_async16(void* smem_ptr, const void* gptr) {
    uint32_t s = (uint32_t)__cvta_generic_to_shared(smem_ptr);
    asm volatile("cp.async.cg.shared.global [%0], [%1], 16;\n" :: "r"(s), "l"(gptr));
}
__device__ __forceinline__ void cp_commit() { asm volatile("cp.async.commit_group;\n"); }
template <int N>
__device__ __forceinline__ void cp_wait() { asm volatile("cp.async.wait_group %0;\n" :: "n"(N)); }

__device__ __forceinline__ void ldsm_x4(uint32_t& r0, uint32_t& r1, uint32_t& r2, uint32_t& r3,
                                        uint32_t addr) {
    asm volatile("ldmatrix.sync.aligned.m8n8.x4.shared.b16 {%0,%1,%2,%3}, [%4];"
                 : "=r"(r0), "=r"(r1), "=r"(r2), "=r"(r3) : "r"(addr));
}

__device__ __forceinline__ void mma_f16(float* c, const uint32_t* a, const uint32_t* b) {
    asm volatile(
        "mma.sync.aligned.m16n8k16.row.col.f32.f16.f16.f32 "
        "{%0,%1,%2,%3}, {%4,%5,%6,%7}, {%8,%9}, {%0,%1,%2,%3};\n"
        : "+f"(c[0]), "+f"(c[1]), "+f"(c[2]), "+f"(c[3])
        : "r"(a[0]), "r"(a[1]), "r"(a[2]), "r"(a[3]), "r"(b[0]), "r"(b[1]));
}

__device__ __forceinline__ uint32_t h2_bits(__half2 h) {
    union { __half2 h; uint32_t u; } cvt;
    cvt.h = h;
    return cvt.u;
}

// Packed fp32x2 helpers (Blackwell FFMA2 path)
__device__ __forceinline__ void fma2(u64b& d, u64b a, u64b b, u64b c) {
    asm("fma.rn.f32x2 %0, %1, %2, %3;" : "=l"(d) : "l"(a), "l"(b), "l"(c));
}
__device__ __forceinline__ u64b pack2(float lo, float hi) {
    u64b p;
    asm("mov.b64 %0, {%1, %2};" : "=l"(p) : "f"(lo), "f"(hi));
    return p;
}
__device__ __forceinline__ void unpack2(float& lo, float& hi, u64b v) {
    asm("mov.b64 {%0, %1}, %2;" : "=f"(lo), "=f"(hi) : "l"(v));
}

// ---------------------------------------------------------------------------
// Kernel 0: W -> fp16
// ---------------------------------------------------------------------------
__global__ void wconv_kernel(const float* __restrict__ W) {
    size_t i = ((size_t)blockIdx.x * 256 + threadIdx.x) * 4;
    float4 v = *(const float4*)(W + i);
    uint2 o;
    o.x = h2_bits(__floats2half2_rn(v.x, v.y));
    o.y = h2_bits(__floats2half2_rn(v.z, v.w));
    *(uint2*)(w_h + i) = o;
}

// ---------------------------------------------------------------------------
// Kernel 1 (v4): conv + 2*D*u + exact GELU, packed f32x2.
// Tile: 128 l x 32 h (16 h-pairs), 128 threads, 16 l-outputs/thread.
// Uses 49 KB; we REQUEST 66 KB at launch to cap residency at 3/SM alone
// and 2/SM beside a 96-KB gemm CTA (2*66 + 96 = 198 <= 228 KB) so gemm
// blocks can co-schedule during the overlap window.
// ---------------------------------------------------------------------------
#define CONV_SMEM_USED ((128 * 16 + 255 * 16) * 8)   // 49024 B
#define CONV_SMEM_ALLOC (66 * 1024)                  // residency governor

__global__ __launch_bounds__(128, 3) void conv_gelu_f32x2(
    const float* __restrict__ u, const float* __restrict__ kern,
    const float* __restrict__ D, int b, int l_base)
{
    extern __shared__ u64b sm2[];
    u64b* ks2 = sm2;               // [j=128][hp=16]
    u64b* us2 = sm2 + 128 * 16;    // [t=255][hp=16]

    const int l0 = l_base + blockIdx.x * 128;
    const int h0 = blockIdx.y * 32;
    const int tid = threadIdx.x;

    for (int idx = tid; idx < 128 * 16; idx += 128) {
        int hp = idx >> 7, j = idx & 127;
        int h = h0 + 2 * hp;
        float v0 = kern[h * LK + j], v1 = kern[(h + 1) * LK + j];
        float a0 = fabsf(v0) - 0.003f; a0 = (a0 > 0.f) ? copysignf(a0, v0) : 0.f;
        float a1 = fabsf(v1) - 0.003f; a1 = (a1 > 0.f) ? copysignf(a1, v1) : 0.f;
        ks2[j * 16 + hp] = pack2(a0, a1);
    }
    const float* ub = u + (size_t)b * LL * HH;
    for (int idx = tid; idx < 255 * 16; idx += 128) {
        int t = idx >> 4, hp = idx & 15;
        int gl = l0 - (LK - 1) + t;
        u64b val = 0ull;
        if (gl >= 0) val = *(const u64b*)(ub + (size_t)gl * HH + h0 + 2 * hp);
        us2[t * 16 + hp] = val;
    }
    __syncthreads();

    const int tx = tid & 15;       // h-pair lane
    const int ty = tid >> 4;       // 0..7
    const int lyb = ty * 16;

    u64b acc[16];
#pragma unroll
    for (int i = 0; i < 16; i++) acc[i] = 0ull;

    for (int j = 0; j < LK; j += 8) {
        u64b kr[8];
#pragma unroll
        for (int jj = 0; jj < 8; jj++) kr[jj] = ks2[(j + jj) * 16 + tx];
        u64b w[23];
        const int tb = 120 + lyb - j;
#pragma unroll
        for (int s = 0; s < 23; s++) w[s] = us2[(tb + s) * 16 + tx];
#pragma unroll
        for (int jj = 0; jj < 8; jj++)
#pragma unroll
            for (int i = 0; i < 16; i++)
                fma2(acc[i], kr[jj], w[7 - jj + i], acc[i]);
    }

    const int h = h0 + 2 * tx;
    const u64b Dv2 = pack2(2.f * D[h], 2.f * D[h + 1]);
#pragma unroll
    for (int i = 0; i < 16; i++) {
        int ly = lyb + i;
        u64b y2;
        fma2(y2, Dv2, us2[(LK - 1 + ly) * 16 + tx], acc[i]);
        float y0, y1;
        unpack2(y0, y1, y2);
        float g0 = y0 * normcdff(y0);
        float g1 = y1 * normcdff(y1);
        *(uint32_t*)(g_buf + ((size_t)b * LL + l0 + ly) * HH + h) =
            h2_bits(__floats2half2_rn(g0, g1));
    }
}

// ---------------------------------------------------------------------------
// Kernel 2 (R7 config — measured best, unchanged): FP16 mma.sync GEMM + GLU.
//   CTA tile: M=128 x 128 B-rows (64 GLU pairs) x K=2048.
//   8 warps: 4(M) x 2(N). 96 KB smem, 2 CTAs/SM, 128 regs.
// ---------------------------------------------------------------------------
#define KST 64                       // k elements per stage (128 B/row)
#define STG_BYTES 16384              // 128 rows * 128 B
#define ST_A 0
#define ST_B (3 * STG_BYTES)
#define SMEM_TOTAL_G (6 * STG_BYTES) // 96 KB

__device__ __forceinline__ uint32_t sw128(uint32_t off) {
    return off ^ ((off >> 3) & 0x70);
}

__global__ __launch_bounds__(256, 2) void gemm_glu_f16(
    const float* __restrict__ bias, float* __restrict__ out, int m_base)
{
    extern __shared__ char smem[];
    const uint32_t sb = (uint32_t)__cvta_generic_to_shared(smem);
    const int tid  = threadIdx.x;
    const int lane = tid & 31;
    const int wid  = tid >> 5;
    const int warpM = wid & 3;
    const int warpN = wid >> 2;
    const int m0  = m_base + blockIdx.y * 128;
    const int nb0 = blockIdx.x * 64;

    auto load_stage = [&](int slot, int k0) {
#pragma unroll
        for (int i = 0; i < 8; i++) {
            int idx = tid + i * 256;
            int row = (idx >> 3) & 127, ch = idx & 7;
            uint32_t sw = sw128(row * 128 + ch * 16);
            if (idx < 1024) {
                cp_async16(smem + ST_A + slot * STG_BYTES + sw,
                           g_buf + (size_t)(m0 + row) * KDIM + k0 + ch * 8);
            } else {
                int q = row >> 1;
                int wrow = (row & 1) ? (NHALF + nb0 + q) : (nb0 + q);
                cp_async16(smem + ST_B + slot * STG_BYTES + sw,
                           w_h + (size_t)wrow * KDIM + k0 + ch * 8);
            }
        }
        cp_commit();
    };

    float acc[2][8][4];
#pragma unroll
    for (int mt = 0; mt < 2; mt++)
#pragma unroll
        for (int nt = 0; nt < 8; nt++)
#pragma unroll
            for (int c = 0; c < 4; c++) acc[mt][nt][c] = 0.f;

    const int NST = KDIM / KST;              // 32
    load_stage(0, 0);
    load_stage(1, KST);

    const uint32_t a_row = warpM * 32 + (lane & 15);
    const uint32_t a_kh8 = (lane >> 4) << 3;
    const uint32_t b_row = warpN * 64 + (lane & 7) + ((lane >> 4) << 3);
    const uint32_t b_kh8 = lane & 8;

    int slot = 0;
    for (int s = 0; s < NST; s++) {
        cp_wait<1>();
        __syncthreads();

        if (s + 2 < NST) {
            int ls = slot + 2; if (ls >= 3) ls -= 3;
            load_stage(ls, (s + 2) * KST);
        }

        const uint32_t abase = sb + ST_A + slot * STG_BYTES;
        const uint32_t bbase = sb + ST_B + slot * STG_BYTES;

#pragma unroll
        for (int k16 = 0; k16 < 4; k16++) {
            const uint32_t kk = k16 * 16;
            uint32_t a[2][4], bf[8][2];
#pragma unroll
            for (int mt = 0; mt < 2; mt++)
                ldsm_x4(a[mt][0], a[mt][1], a[mt][2], a[mt][3],
                        abase + sw128((a_row + mt * 16) * 128 + (kk + a_kh8) * 2));
#pragma unroll
            for (int nt2 = 0; nt2 < 4; nt2++)
                ldsm_x4(bf[2 * nt2][0], bf[2 * nt2][1], bf[2 * nt2 + 1][0], bf[2 * nt2 + 1][1],
                        bbase + sw128((b_row + nt2 * 16) * 128 + (kk + b_kh8) * 2));
#pragma unroll
            for (int mt = 0; mt < 2; mt++)
#pragma unroll
                for (int nt = 0; nt < 8; nt++)
                    mma_f16(acc[mt][nt], a[mt], bf[nt]);
        }

        if (++slot >= 3) slot = 0;
    }

#pragma unroll
    for (int mt = 0; mt < 2; mt++) {
        int row = m0 + warpM * 32 + mt * 16 + (lane >> 2);
#pragma unroll
        for (int nt = 0; nt < 8; nt++) {
            int col = nb0 + warpN * 32 + nt * 4 + (lane & 3);
            float ba = __ldg(bias + col);
            float bg = __ldg(bias + NHALF + col);

            float za0 = acc[mt][nt][0] + ba;
            float zg0 = acc[mt][nt][1] + bg;
            out[(size_t)row * NHALF + col] = za0 * (1.f / (1.f + __expf(-zg0)));

            float za1 = acc[mt][nt][2] + ba;
            float zg1 = acc[mt][nt][3] + bg;
            out[(size_t)(row + 8) * NHALF + col] = za1 * (1.f / (1.f + __expf(-zg1)));
        }
    }
}

// ---------------------------------------------------------------------------
// Launch: 4 chunks of 2048 rows. conv chunk c+1.. overlaps gemm chunk c;
// conv's inflated smem request guarantees gemm CTAs can co-schedule.
// ---------------------------------------------------------------------------
#define NCHUNK 4
#define MCHUNK ((BB * LL) / NCHUNK)   // 2048 rows

extern "C" void kernel_launch(void* const* d_in, const int* in_sizes, int n_in,
                              void* d_out, int out_size)
{
    const float* u    = (const float*)d_in[0];  // [2,4096,2048]
    const float* kern = (const float*)d_in[1];  // [1,2048,128]
    const float* D    = (const float*)d_in[2];  // [1,2048]
    const float* W    = (const float*)d_in[3];  // [4096,2048]
    const float* bias = (const float*)d_in[4];  // [4096]
    float* out = (float*)d_out;                 // [2,4096,2048]

    static cudaStream_t s_gemm = nullptr;
    static cudaEvent_t ev_conv[NCHUNK];
    static cudaEvent_t ev_done;
    if (s_gemm == nullptr) {
        cudaStreamCreateWithFlags(&s_gemm, cudaStreamNonBlocking);
        for (int c = 0; c < NCHUNK; c++)
            cudaEventCreateWithFlags(&ev_conv[c], cudaEventDisableTiming);
        cudaEventCreateWithFlags(&ev_done, cudaEventDisableTiming);
        cudaFuncSetAttribute(gemm_glu_f16, cudaFuncAttributeMaxDynamicSharedMemorySize,
                             SMEM_TOTAL_G);
        cudaFuncSetAttribute(conv_gelu_f32x2, cudaFuncAttributeMaxDynamicSharedMemorySize,
                             CONV_SMEM_ALLOC);
    }

    wconv_kernel<<<8192, 256>>>(W);

    for (int c = 0; c < NCHUNK; c++) {
        int b = c >> 1;
        int l_base = (c & 1) * MCHUNK;   // MCHUNK == LL/2
        conv_gelu_f32x2<<<dim3(MCHUNK / 128, HH / 32), 128, CONV_SMEM_ALLOC>>>(
            u, kern, D, b, l_base);
        cudaEventRecord(ev_conv[c], 0);
    }

    for (int c = 0; c < NCHUNK; c++) {
        cudaStreamWaitEvent(s_gemm, ev_conv[c], 0);
        gemm_glu_f16<<<dim3(NHALF / 64, MCHUNK / 128), 256, SMEM_TOTAL_G, s_gemm>>>(
            bias, out, c * MCHUNK);
    }

    cudaEventRecord(ev_done, s_gemm);
    cudaStreamWaitEvent(0, ev_done, 0);
}

// round 11
// speedup vs baseline: 1.1270x; 1.1270x over previous
#include <cuda_runtime.h>
#include <cuda_fp16.h>
#include <cstdint>
#include <math.h>

// Problem constants
#define BB 2
#define LL 4096
#define HH 2048
#define LK 128
#define KDIM HH          // GEMM K = H = 2048
#define NHALF HH         // GLU half width = 2048

typedef unsigned long long u64b;

// Scratch (static __device__ arrays: allocation-free per harness rules)
__device__ __half g_buf[(size_t)BB * LL * HH];   // gelu(conv) output fp16, [M=B*L, K=H]
__device__ __half w_h[(size_t)2 * HH * HH];      // W fp16, [4096, 2048]

__device__ __forceinline__ void cp_async16(void* smem_ptr, const void* gptr) {
    uint32_t s = (uint32_t)__cvta_generic_to_shared(smem_ptr);
    asm volatile("cp.async.cg.shared.global [%0], [%1], 16;\n" :: "r"(s), "l"(gptr));
}
__device__ __forceinline__ void cp_commit() { asm volatile("cp.async.commit_group;\n"); }
template <int N>
__device__ __forceinline__ void cp_wait() { asm volatile("cp.async.wait_group %0;\n" :: "n"(N)); }

__device__ __forceinline__ void ldsm_x4(uint32_t& r0, uint32_t& r1, uint32_t& r2, uint32_t& r3,
                                        uint32_t addr) {
    asm volatile("ldmatrix.sync.aligned.m8n8.x4.shared.b16 {%0,%1,%2,%3}, [%4];"
                 : "=r"(r0), "=r"(r1), "=r"(r2), "=r"(r3) : "r"(addr));
}

__device__ __forceinline__ void mma_f16(float* c, const uint32_t* a, const uint32_t* b) {
    asm volatile(
        "mma.sync.aligned.m16n8k16.row.col.f32.f16.f16.f32 "
        "{%0,%1,%2,%3}, {%4,%5,%6,%7}, {%8,%9}, {%0,%1,%2,%3};\n"
        : "+f"(c[0]), "+f"(c[1]), "+f"(c[2]), "+f"(c[3])
        : "r"(a[0]), "r"(a[1]), "r"(a[2]), "r"(a[3]), "r"(b[0]), "r"(b[1]));
}

__device__ __forceinline__ uint32_t h2_bits(__half2 h) {
    union { __half2 h; uint32_t u; } cvt;
    cvt.h = h;
    return cvt.u;
}

// Packed fp32x2 helpers (Blackwell FFMA2 path)
__device__ __forceinline__ void fma2(u64b& d, u64b a, u64b b, u64b c) {
    asm("fma.rn.f32x2 %0, %1, %2, %3;" : "=l"(d) : "l"(a), "l"(b), "l"(c));
}
__device__ __forceinline__ u64b pack2(float lo, float hi) {
    u64b p;
    asm("mov.b64 %0, {%1, %2};" : "=l"(p) : "f"(lo), "f"(hi));
    return p;
}
__device__ __forceinline__ void unpack2(float& lo, float& hi, u64b v) {
    asm("mov.b64 {%0, %1}, %2;" : "=f"(lo), "=f"(hi) : "l"(v));
}

// ---------------------------------------------------------------------------
// Kernel 0: W -> fp16
// ---------------------------------------------------------------------------
__global__ void wconv_kernel(const float* __restrict__ W) {
    size_t i = ((size_t)blockIdx.x * 256 + threadIdx.x) * 4;
    float4 v = *(const float4*)(W + i);
    uint2 o;
    o.x = h2_bits(__floats2half2_rn(v.x, v.y));
    o.y = h2_bits(__floats2half2_rn(v.z, v.w));
    *(uint2*)(w_h + i) = o;
}

// ---------------------------------------------------------------------------
// Kernel 1 (v5): conv + 2*D*u + exact GELU, packed f32x2.
// Tile: 256 l x 32 h (16 h-pairs), 256 threads, 16 l-outputs/thread.
// Same 31-LDS-per-128-FFMA2 inner loop as v4, but 65 KB smem -> 3 CTAs/SM
// -> 24 warps/SM (6/SMSP) for latency hiding; regs pinned <=85 by bounds.
// ---------------------------------------------------------------------------
#define CONV_SMEM ((128 * 16 + 383 * 16) * 8)   // 65408 B

__global__ __launch_bounds__(256, 3) void conv_gelu_f32x2(
    const float* __restrict__ u, const float* __restrict__ kern,
    const float* __restrict__ D, int b)
{
    extern __shared__ u64b sm2[];
    u64b* ks2 = sm2;               // [j=128][hp=16]
    u64b* us2 = sm2 + 128 * 16;    // [t=383][hp=16]

    const int l0 = blockIdx.x * 256;
    const int h0 = blockIdx.y * 32;
    const int tid = threadIdx.x;

    for (int idx = tid; idx < 128 * 16; idx += 256) {
        int hp = idx >> 7, j = idx & 127;
        int h = h0 + 2 * hp;
        float v0 = kern[h * LK + j], v1 = kern[(h + 1) * LK + j];
        float a0 = fabsf(v0) - 0.003f; a0 = (a0 > 0.f) ? copysignf(a0, v0) : 0.f;
        float a1 = fabsf(v1) - 0.003f; a1 = (a1 > 0.f) ? copysignf(a1, v1) : 0.f;
        ks2[j * 16 + hp] = pack2(a0, a1);
    }
    const float* ub = u + (size_t)b * LL * HH;
    for (int idx = tid; idx < 383 * 16; idx += 256) {
        int t = idx >> 4, hp = idx & 15;
        int gl = l0 - (LK - 1) + t;
        u64b val = 0ull;
        if (gl >= 0) val = *(const u64b*)(ub + (size_t)gl * HH + h0 + 2 * hp);
        us2[t * 16 + hp] = val;
    }
    __syncthreads();

    const int tx = tid & 15;       // h-pair lane
    const int ty = tid >> 4;       // 0..15
    const int lyb = ty * 16;

    u64b acc[16];
#pragma unroll
    for (int i = 0; i < 16; i++) acc[i] = 0ull;

    for (int j = 0; j < LK; j += 8) {
        u64b kr[8];
#pragma unroll
        for (int jj = 0; jj < 8; jj++) kr[jj] = ks2[(j + jj) * 16 + tx];
        u64b w[23];
        const int tb = 120 + lyb - j;
#pragma unroll
        for (int s = 0; s < 23; s++) w[s] = us2[(tb + s) * 16 + tx];
#pragma unroll
        for (int jj = 0; jj < 8; jj++)
#pragma unroll
            for (int i = 0; i < 16; i++)
                fma2(acc[i], kr[jj], w[7 - jj + i], acc[i]);
    }

    const int h = h0 + 2 * tx;
    const u64b Dv2 = pack2(2.f * D[h], 2.f * D[h + 1]);
#pragma unroll
    for (int i = 0; i < 16; i++) {
        int ly = lyb + i;
        u64b y2;
        fma2(y2, Dv2, us2[(LK - 1 + ly) * 16 + tx], acc[i]);
        float y0, y1;
        unpack2(y0, y1, y2);
        float g0 = y0 * normcdff(y0);
        float g1 = y1 * normcdff(y1);
        *(uint32_t*)(g_buf + ((size_t)b * LL + l0 + ly) * HH + h) =
            h2_bits(__floats2half2_rn(g0, g1));
    }
}

// ---------------------------------------------------------------------------
// Kernel 2 (R7/R9 config — measured best, unchanged): FP16 mma.sync GEMM + GLU.
//   CTA tile: M=128 x 128 B-rows (64 GLU pairs) x K=2048.
//   8 warps: 4(M) x 2(N). 96 KB smem, 2 CTAs/SM, 128 regs.
// ---------------------------------------------------------------------------
#define KST 64                       // k elements per stage (128 B/row)
#define STG_BYTES 16384              // 128 rows * 128 B
#define ST_A 0
#define ST_B (3 * STG_BYTES)
#define SMEM_TOTAL_G (6 * STG_BYTES) // 96 KB

__device__ __forceinline__ uint32_t sw128(uint32_t off) {
    return off ^ ((off >> 3) & 0x70);
}

__global__ __launch_bounds__(256, 2) void gemm_glu_f16(
    const float* __restrict__ bias, float* __restrict__ out, int m_base)
{
    extern __shared__ char smem[];
    const uint32_t sb = (uint32_t)__cvta_generic_to_shared(smem);
    const int tid  = threadIdx.x;
    const int lane = tid & 31;
    const int wid  = tid >> 5;
    const int warpM = wid & 3;
    const int warpN = wid >> 2;
    const int m0  = m_base + blockIdx.y * 128;
    const int nb0 = blockIdx.x * 64;

    auto load_stage = [&](int slot, int k0) {
#pragma unroll
        for (int i = 0; i < 8; i++) {
            int idx = tid + i * 256;
            int row = (idx >> 3) & 127, ch = idx & 7;
            uint32_t sw = sw128(row * 128 + ch * 16);
            if (idx < 1024) {
                cp_async16(smem + ST_A + slot * STG_BYTES + sw,
                           g_buf + (size_t)(m0 + row) * KDIM + k0 + ch * 8);
            } else {
                int q = row >> 1;
                int wrow = (row & 1) ? (NHALF + nb0 + q) : (nb0 + q);
                cp_async16(smem + ST_B + slot * STG_BYTES + sw,
                           w_h + (size_t)wrow * KDIM + k0 + ch * 8);
            }
        }
        cp_commit();
    };

    float acc[2][8][4];
#pragma unroll
    for (int mt = 0; mt < 2; mt++)
#pragma unroll
        for (int nt = 0; nt < 8; nt++)
#pragma unroll
            for (int c = 0; c < 4; c++) acc[mt][nt][c] = 0.f;

    const int NST = KDIM / KST;              // 32
    load_stage(0, 0);
    load_stage(1, KST);

    const uint32_t a_row = warpM * 32 + (lane & 15);
    const uint32_t a_kh8 = (lane >> 4) << 3;
    const uint32_t b_row = warpN * 64 + (lane & 7) + ((lane >> 4) << 3);
    const uint32_t b_kh8 = lane & 8;

    int slot = 0;
    for (int s = 0; s < NST; s++) {
        cp_wait<1>();
        __syncthreads();

        if (s + 2 < NST) {
            int ls = slot + 2; if (ls >= 3) ls -= 3;
            load_stage(ls, (s + 2) * KST);
        }

        const uint32_t abase = sb + ST_A + slot * STG_BYTES;
        const uint32_t bbase = sb + ST_B + slot * STG_BYTES;

#pragma unroll
        for (int k16 = 0; k16 < 4; k16++) {
            const uint32_t kk = k16 * 16;
            uint32_t a[2][4], bf[8][2];
#pragma unroll
            for (int mt = 0; mt < 2; mt++)
                ldsm_x4(a[mt][0], a[mt][1], a[mt][2], a[mt][3],
                        abase + sw128((a_row + mt * 16) * 128 + (kk + a_kh8) * 2));
#pragma unroll
            for (int nt2 = 0; nt2 < 4; nt2++)
                ldsm_x4(bf[2 * nt2][0], bf[2 * nt2][1], bf[2 * nt2 + 1][0], bf[2 * nt2 + 1][1],
                        bbase + sw128((b_row + nt2 * 16) * 128 + (kk + b_kh8) * 2));
#pragma unroll
            for (int mt = 0; mt < 2; mt++)
#pragma unroll
                for (int nt = 0; nt < 8; nt++)
                    mma_f16(acc[mt][nt], a[mt], bf[nt]);
        }

        if (++slot >= 3) slot = 0;
    }

#pragma unroll
    for (int mt = 0; mt < 2; mt++) {
        int row = m0 + warpM * 32 + mt * 16 + (lane >> 2);
#pragma unroll
        for (int nt = 0; nt < 8; nt++) {
            int col = nb0 + warpN * 32 + nt * 4 + (lane & 3);
            float ba = __ldg(bias + col);
            float bg = __ldg(bias + NHALF + col);

            float za0 = acc[mt][nt][0] + ba;
            float zg0 = acc[mt][nt][1] + bg;
            out[(size_t)row * NHALF + col] = za0 * (1.f / (1.f + __expf(-zg0)));

            float za1 = acc[mt][nt][2] + ba;
            float zg1 = acc[mt][nt][3] + bg;
            out[(size_t)(row + 8) * NHALF + col] = za1 * (1.f / (1.f + __expf(-zg1)));
        }
    }
}

// ---------------------------------------------------------------------------
// Launch (R9 structure): 2 chunks, one per batch; cross-stream event pipeline
// gives free tail overlap.
// ---------------------------------------------------------------------------
#define NCHUNK 2
#define MCHUNK ((BB * LL) / NCHUNK)   // 4096 rows = one batch

extern "C" void kernel_launch(void* const* d_in, const int* in_sizes, int n_in,
                              void* d_out, int out_size)
{
    const float* u    = (const float*)d_in[0];  // [2,4096,2048]
    const float* kern = (const float*)d_in[1];  // [1,2048,128]
    const float* D    = (const float*)d_in[2];  // [1,2048]
    const float* W    = (const float*)d_in[3];  // [4096,2048]
    const float* bias = (const float*)d_in[4];  // [4096]
    float* out = (float*)d_out;                 // [2,4096,2048]

    static cudaStream_t s_gemm = nullptr;
    static cudaEvent_t ev_conv[NCHUNK];
    static cudaEvent_t ev_done;
    if (s_gemm == nullptr) {
        cudaStreamCreateWithFlags(&s_gemm, cudaStreamNonBlocking);
        for (int c = 0; c < NCHUNK; c++)
            cudaEventCreateWithFlags(&ev_conv[c], cudaEventDisableTiming);
        cudaEventCreateWithFlags(&ev_done, cudaEventDisableTiming);
        cudaFuncSetAttribute(gemm_glu_f16, cudaFuncAttributeMaxDynamicSharedMemorySize,
                             SMEM_TOTAL_G);
        cudaFuncSetAttribute(conv_gelu_f32x2, cudaFuncAttributeMaxDynamicSharedMemorySize,
                             CONV_SMEM);
    }

    wconv_kernel<<<8192, 256>>>(W);

    for (int c = 0; c < NCHUNK; c++) {
        conv_gelu_f32x2<<<dim3(LL / 256, HH / 32), 256, CONV_SMEM>>>(u, kern, D, c);
        cudaEventRecord(ev_conv[c], 0);
    }

    for (int c = 0; c < NCHUNK; c++) {
        cudaStreamWaitEvent(s_gemm, ev_conv[c], 0);
        gemm_glu_f16<<<dim3(NHALF / 64, MCHUNK / 128), 256, SMEM_TOTAL_G, s_gemm>>>(
            bias, out, c * MCHUNK);
    }

    cudaEventRecord(ev_done, s_gemm);
    cudaStreamWaitEvent(0, ev_done, 0);
}

// round 13
// speedup vs baseline: 1.1495x; 1.0199x over previous
#include <cuda_runtime.h>
#include <cuda_fp16.h>
#include <cstdint>
#include <math.h>

// Problem constants
#define BB 2
#define LL 4096
#define HH 2048
#define LK 128
#define KDIM HH          // GEMM K = H = 2048
#define NHALF HH         // GLU half width = 2048

typedef unsigned long long u64b;

// Scratch (static __device__ arrays: allocation-free per harness rules)
__device__ __half g_buf[(size_t)BB * LL * HH];   // gelu(conv) output fp16, [M=B*L, K=H]
__device__ __half w_h[(size_t)2 * HH * HH];      // W fp16, [4096, 2048]

__device__ __forceinline__ void cp_async16(void* smem_ptr, const void* gptr) {
    uint32_t s = (uint32_t)__cvta_generic_to_shared(smem_ptr);
    asm volatile("cp.async.cg.shared.global [%0], [%1], 16;\n" :: "r"(s), "l"(gptr));
}
__device__ __forceinline__ void cp_commit() { asm volatile("cp.async.commit_group;\n"); }
template <int N>
__device__ __forceinline__ void cp_wait() { asm volatile("cp.async.wait_group %0;\n" :: "n"(N)); }

__device__ __forceinline__ void ldsm_x4(uint32_t& r0, uint32_t& r1, uint32_t& r2, uint32_t& r3,
                                        uint32_t addr) {
    asm volatile("ldmatrix.sync.aligned.m8n8.x4.shared.b16 {%0,%1,%2,%3}, [%4];"
                 : "=r"(r0), "=r"(r1), "=r"(r2), "=r"(r3) : "r"(addr));
}

__device__ __forceinline__ void mma_f16(float* c, const uint32_t* a, const uint32_t* b) {
    asm volatile(
        "mma.sync.aligned.m16n8k16.row.col.f32.f16.f16.f32 "
        "{%0,%1,%2,%3}, {%4,%5,%6,%7}, {%8,%9}, {%0,%1,%2,%3};\n"
        : "+f"(c[0]), "+f"(c[1]), "+f"(c[2]), "+f"(c[3])
        : "r"(a[0]), "r"(a[1]), "r"(a[2]), "r"(a[3]), "r"(b[0]), "r"(b[1]));
}

__device__ __forceinline__ uint32_t h2_bits(__half2 h) {
    union { __half2 h; uint32_t u; } cvt;
    cvt.h = h;
    return cvt.u;
}

// Packed fp32x2 helpers (Blackwell FFMA2 path)
__device__ __forceinline__ void fma2(u64b& d, u64b a, u64b b, u64b c) {
    asm("fma.rn.f32x2 %0, %1, %2, %3;" : "=l"(d) : "l"(a), "l"(b), "l"(c));
}
__device__ __forceinline__ u64b pack2(float lo, float hi) {
    u64b p;
    asm("mov.b64 %0, {%1, %2};" : "=l"(p) : "f"(lo), "f"(hi));
    return p;
}
__device__ __forceinline__ void unpack2(float& lo, float& hi, u64b v) {
    asm("mov.b64 {%0, %1}, %2;" : "=f"(lo), "=f"(hi) : "l"(v));
}

// ---------------------------------------------------------------------------
// Kernel 0: W -> fp16
// ---------------------------------------------------------------------------
__global__ void wconv_kernel(const float* __restrict__ W) {
    size_t i = ((size_t)blockIdx.x * 256 + threadIdx.x) * 4;
    float4 v = *(const float4*)(W + i);
    uint2 o;
    o.x = h2_bits(__floats2half2_rn(v.x, v.y));
    o.y = h2_bits(__floats2half2_rn(v.z, v.w));
    *(uint2*)(w_h + i) = o;
}

// ---------------------------------------------------------------------------
// Kernel 1 (v5, unchanged — measured best): conv + 2*D*u + exact GELU, f32x2.
// Tile: 256 l x 32 h (16 h-pairs), 256 threads, 16 l-outputs/thread.
// 65 KB smem -> 3 CTAs/SM -> 24 warps/SM.
// ---------------------------------------------------------------------------
#define CONV_SMEM ((128 * 16 + 383 * 16) * 8)   // 65408 B

__global__ __launch_bounds__(256, 3) void conv_gelu_f32x2(
    const float* __restrict__ u, const float* __restrict__ kern,
    const float* __restrict__ D, int b)
{
    extern __shared__ u64b sm2[];
    u64b* ks2 = sm2;               // [j=128][hp=16]
    u64b* us2 = sm2 + 128 * 16;    // [t=383][hp=16]

    const int l0 = blockIdx.x * 256;
    const int h0 = blockIdx.y * 32;
    const int tid = threadIdx.x;

    for (int idx = tid; idx < 128 * 16; idx += 256) {
        int hp = idx >> 7, j = idx & 127;
        int h = h0 + 2 * hp;
        float v0 = kern[h * LK + j], v1 = kern[(h + 1) * LK + j];
        float a0 = fabsf(v0) - 0.003f; a0 = (a0 > 0.f) ? copysignf(a0, v0) : 0.f;
        float a1 = fabsf(v1) - 0.003f; a1 = (a1 > 0.f) ? copysignf(a1, v1) : 0.f;
        ks2[j * 16 + hp] = pack2(a0, a1);
    }
    const float* ub = u + (size_t)b * LL * HH;
    for (int idx = tid; idx < 383 * 16; idx += 256) {
        int t = idx >> 4, hp = idx & 15;
        int gl = l0 - (LK - 1) + t;
        u64b val = 0ull;
        if (gl >= 0) val = *(const u64b*)(ub + (size_t)gl * HH + h0 + 2 * hp);
        us2[t * 16 + hp] = val;
    }
    __syncthreads();

    const int tx = tid & 15;       // h-pair lane
    const int ty = tid >> 4;       // 0..15
    const int lyb = ty * 16;

    u64b acc[16];
#pragma unroll
    for (int i = 0; i < 16; i++) acc[i] = 0ull;

    for (int j = 0; j < LK; j += 8) {
        u64b kr[8];
#pragma unroll
        for (int jj = 0; jj < 8; jj++) kr[jj] = ks2[(j + jj) * 16 + tx];
        u64b w[23];
        const int tb = 120 + lyb - j;
#pragma unroll
        for (int s = 0; s < 23; s++) w[s] = us2[(tb + s) * 16 + tx];
#pragma unroll
        for (int jj = 0; jj < 8; jj++)
#pragma unroll
            for (int i = 0; i < 16; i++)
                fma2(acc[i], kr[jj], w[7 - jj + i], acc[i]);
    }

    const int h = h0 + 2 * tx;
    const u64b Dv2 = pack2(2.f * D[h], 2.f * D[h + 1]);
#pragma unroll
    for (int i = 0; i < 16; i++) {
        int ly = lyb + i;
        u64b y2;
        fma2(y2, Dv2, us2[(LK - 1 + ly) * 16 + tx], acc[i]);
        float y0, y1;
        unpack2(y0, y1, y2);
        float g0 = y0 * normcdff(y0);
        float g1 = y1 * normcdff(y1);
        *(uint32_t*)(g_buf + ((size_t)b * LL + l0 + ly) * HH + h) =
            h2_bits(__floats2half2_rn(g0, g1));
    }
}

// ---------------------------------------------------------------------------
// Kernel 2 (unchanged — measured best): FP16 mma.sync GEMM + fused GLU.
//   CTA tile: M=128 x 128 B-rows (64 GLU pairs) x K=2048.
//   8 warps: 4(M) x 2(N). 96 KB smem, 2 CTAs/SM, 128 regs.
// ---------------------------------------------------------------------------
#define KST 64                       // k elements per stage (128 B/row)
#define STG_BYTES 16384              // 128 rows * 128 B
#define ST_A 0
#define ST_B (3 * STG_BYTES)
#define SMEM_TOTAL_G (6 * STG_BYTES) // 96 KB

__device__ __forceinline__ uint32_t sw128(uint32_t off) {
    return off ^ ((off >> 3) & 0x70);
}

__global__ __launch_bounds__(256, 2) void gemm_glu_f16(
    const float* __restrict__ bias, float* __restrict__ out, int m_base)
{
    extern __shared__ char smem[];
    const uint32_t sb = (uint32_t)__cvta_generic_to_shared(smem);
    const int tid  = threadIdx.x;
    const int lane = tid & 31;
    const int wid  = tid >> 5;
    const int warpM = wid & 3;
    const int warpN = wid >> 2;
    const int m0  = m_base + blockIdx.y * 128;
    const int nb0 = blockIdx.x * 64;

    auto load_stage = [&](int slot, int k0) {
#pragma unroll
        for (int i = 0; i < 8; i++) {
            int idx = tid + i * 256;
            int row = (idx >> 3) & 127, ch = idx & 7;
            uint32_t sw = sw128(row * 128 + ch * 16);
            if (idx < 1024) {
                cp_async16(smem + ST_A + slot * STG_BYTES + sw,
                           g_buf + (size_t)(m0 + row) * KDIM + k0 + ch * 8);
            } else {
                int q = row >> 1;
                int wrow = (row & 1) ? (NHALF + nb0 + q) : (nb0 + q);
                cp_async16(smem + ST_B + slot * STG_BYTES + sw,
                           w_h + (size_t)wrow * KDIM + k0 + ch * 8);
            }
        }
        cp_commit();
    };

    float acc[2][8][4];
#pragma unroll
    for (int mt = 0; mt < 2; mt++)
#pragma unroll
        for (int nt = 0; nt < 8; nt++)
#pragma unroll
            for (int c = 0; c < 4; c++) acc[mt][nt][c] = 0.f;

    const int NST = KDIM / KST;              // 32
    load_stage(0, 0);
    load_stage(1, KST);

    const uint32_t a_row = warpM * 32 + (lane & 15);
    const uint32_t a_kh8 = (lane >> 4) << 3;
    const uint32_t b_row = warpN * 64 + (lane & 7) + ((lane >> 4) << 3);
    const uint32_t b_kh8 = lane & 8;

    int slot = 0;
    for (int s = 0; s < NST; s++) {
        cp_wait<1>();
        __syncthreads();

        if (s + 2 < NST) {
            int ls = slot + 2; if (ls >= 3) ls -= 3;
            load_stage(ls, (s + 2) * KST);
        }

        const uint32_t abase = sb + ST_A + slot * STG_BYTES;
        const uint32_t bbase = sb + ST_B + slot * STG_BYTES;

#pragma unroll
        for (int k16 = 0; k16 < 4; k16++) {
            const uint32_t kk = k16 * 16;
            uint32_t a[2][4], bf[8][2];
#pragma unroll
            for (int mt = 0; mt < 2; mt++)
                ldsm_x4(a[mt][0], a[mt][1], a[mt][2], a[mt][3],
                        abase + sw128((a_row + mt * 16) * 128 + (kk + a_kh8) * 2));
#pragma unroll
            for (int nt2 = 0; nt2 < 4; nt2++)
                ldsm_x4(bf[2 * nt2][0], bf[2 * nt2][1], bf[2 * nt2 + 1][0], bf[2 * nt2 + 1][1],
                        bbase + sw128((b_row + nt2 * 16) * 128 + (kk + b_kh8) * 2));
#pragma unroll
            for (int mt = 0; mt < 2; mt++)
#pragma unroll
                for (int nt = 0; nt < 8; nt++)
                    mma_f16(acc[mt][nt], a[mt], bf[nt]);
        }

        if (++slot >= 3) slot = 0;
    }

#pragma unroll
    for (int mt = 0; mt < 2; mt++) {
        int row = m0 + warpM * 32 + mt * 16 + (lane >> 2);
#pragma unroll
        for (int nt = 0; nt < 8; nt++) {
            int col = nb0 + warpN * 32 + nt * 4 + (lane & 3);
            float ba = __ldg(bias + col);
            float bg = __ldg(bias + NHALF + col);

            float za0 = acc[mt][nt][0] + ba;
            float zg0 = acc[mt][nt][1] + bg;
            out[(size_t)row * NHALF + col] = za0 * (1.f / (1.f + __expf(-zg0)));

            float za1 = acc[mt][nt][2] + ba;
            float zg1 = acc[mt][nt][3] + bg;
            out[(size_t)(row + 8) * NHALF + col] = za1 * (1.f / (1.f + __expf(-zg1)));
        }
    }
}

// ---------------------------------------------------------------------------
// Launch. Capture-safe stream topology: every side stream is forked from the
// capture-origin stream (stream 0) via an event-wait BEFORE its first launch.
//   stream 0: ev_root -> conv c0 -> ev_conv0 -> conv c1 -> ev_conv1 -> join
//   s_w:      wait ev_root -> wconv -> ev_w
//   s_g[c]:   wait ev_conv[c] + ev_w -> gemm c -> ev_g[c]
// Dual gemm streams let chunk 1's CTAs backfill chunk 0's tail wave.
// ---------------------------------------------------------------------------
#define NCHUNK 2
#define MCHUNK ((BB * LL) / NCHUNK)   // 4096 rows = one batch

extern "C" void kernel_launch(void* const* d_in, const int* in_sizes, int n_in,
                              void* d_out, int out_size)
{
    const float* u    = (const float*)d_in[0];  // [2,4096,2048]
    const float* kern = (const float*)d_in[1];  // [1,2048,128]
    const float* D    = (const float*)d_in[2];  // [1,2048]
    const float* W    = (const float*)d_in[3];  // [4096,2048]
    const float* bias = (const float*)d_in[4];  // [4096]
    float* out = (float*)d_out;                 // [2,4096,2048]

    static cudaStream_t s_w = nullptr;
    static cudaStream_t s_g[NCHUNK];
    static cudaEvent_t ev_root, ev_w;
    static cudaEvent_t ev_conv[NCHUNK];
    static cudaEvent_t ev_g[NCHUNK];
    if (s_w == nullptr) {
        cudaStreamCreateWithFlags(&s_w, cudaStreamNonBlocking);
        cudaEventCreateWithFlags(&ev_root, cudaEventDisableTiming);
        cudaEventCreateWithFlags(&ev_w, cudaEventDisableTiming);
        for (int c = 0; c < NCHUNK; c++) {
            cudaStreamCreateWithFlags(&s_g[c], cudaStreamNonBlocking);
            cudaEventCreateWithFlags(&ev_conv[c], cudaEventDisableTiming);
            cudaEventCreateWithFlags(&ev_g[c], cudaEventDisableTiming);
        }
        cudaFuncSetAttribute(gemm_glu_f16, cudaFuncAttributeMaxDynamicSharedMemorySize,
                             SMEM_TOTAL_G);
        cudaFuncSetAttribute(conv_gelu_f32x2, cudaFuncAttributeMaxDynamicSharedMemorySize,
                             CONV_SMEM);
    }

    // Fork point for side streams (required for graph capture).
    cudaEventRecord(ev_root, 0);

    // W conversion off the critical path, forked from stream 0.
    cudaStreamWaitEvent(s_w, ev_root, 0);
    wconv_kernel<<<8192, 256, 0, s_w>>>(W);
    cudaEventRecord(ev_w, s_w);

    for (int c = 0; c < NCHUNK; c++) {
        conv_gelu_f32x2<<<dim3(LL / 256, HH / 32), 256, CONV_SMEM>>>(u, kern, D, c);
        cudaEventRecord(ev_conv[c], 0);
    }

    for (int c = 0; c < NCHUNK; c++) {
        cudaStreamWaitEvent(s_g[c], ev_conv[c], 0);
        cudaStreamWaitEvent(s_g[c], ev_w, 0);
        gemm_glu_f16<<<dim3(NHALF / 64, MCHUNK / 128), 256, SMEM_TOTAL_G, s_g[c]>>>(
            bias, out, c * MCHUNK);
        cudaEventRecord(ev_g[c], s_g[c]);
    }

    for (int c = 0; c < NCHUNK; c++)
        cudaStreamWaitEvent(0, ev_g[c], 0);
}